// round 12
// baseline (speedup 1.0000x reference)
#include <cuda_runtime.h>
#include <cuda_bf16.h>
#include <cuda_fp16.h>
#include <stdint.h>

#define NN 100000
#define NE 1600000
#define KD 256
#define FD 128   // HEADS*OUT_DIM
#define OD 32
#define NEG 0.2f

#define NSCAN_BLK 98
#define NBIN (NSCAN_BLK * 1024)  // 100352 >= NN

// Scratch (allocation-free rule: __device__ globals)
__device__ __half g_feath[(size_t)NN * FD];  // 25.6 MB fp16 feat
__device__ float g_el[NN * 4];
__device__ float g_er[NN * 4];
__device__ __nv_bfloat16 g_Wt_hi[128 * 256];
__device__ __nv_bfloat16 g_Wt_lo[128 * 256];
// CSR scratch
__device__ unsigned g_cnt[NBIN];
__device__ unsigned g_off[NBIN];    // segment begin
__device__ unsigned g_offw[NBIN];   // working ptr; == segment end after scatter
__device__ unsigned g_bsum[NSCAN_BLK];
__device__ unsigned g_bpre[NSCAN_BLK];
__device__ int g_csrc[NE];

__device__ __forceinline__ float lrelu(float v) { return v > 0.f ? v : NEG * v; }

// ---------------------------------------------------------------------------
__global__ void k_init() {
    int i = blockIdx.x * 256 + threadIdx.x;
    if (i < NBIN) g_cnt[i] = 0u;
}

// ---------------------------------------------------------------------------
__global__ void k_prep(const float* __restrict__ W) {
    int i = blockIdx.x * 256 + threadIdx.x;
    if (i >= 256 * 128) return;
    int k = i >> 7, n = i & 127;
    float w = W[i];
    __nv_bfloat16 h = __float2bfloat16_rn(w);
    float l = w - __bfloat162float(h);
    g_Wt_hi[n * 256 + k] = h;
    g_Wt_lo[n * 256 + k] = __float2bfloat16_rn(l);
}

// ---------------------------------------------------------------------------
// HMMA GEMM (unchanged): 3-term bf16 split, fused el/er epilogue, fp16 feat.
// ---------------------------------------------------------------------------
#define LDA 40

__device__ __forceinline__ void mma16816(float* c, const uint32_t* a, const uint32_t* b) {
    asm volatile(
        "mma.sync.aligned.m16n8k16.row.col.f32.bf16.bf16.f32 "
        "{%0,%1,%2,%3}, {%4,%5,%6,%7}, {%8,%9}, {%0,%1,%2,%3};"
        : "+f"(c[0]), "+f"(c[1]), "+f"(c[2]), "+f"(c[3])
        : "r"(a[0]), "r"(a[1]), "r"(a[2]), "r"(a[3]), "r"(b[0]), "r"(b[1]));
}

__global__ __launch_bounds__(128) void k_gemm_mma(const float* __restrict__ A,
                                                  const float* __restrict__ al,
                                                  const float* __restrict__ ar) {
    __shared__ __align__(16) uint16_t sAhi[128 * LDA];
    __shared__ __align__(16) uint16_t sAlo[128 * LDA];
    __shared__ __align__(16) uint16_t sBhi[128 * LDA];
    __shared__ __align__(16) uint16_t sBlo[128 * LDA];
    __shared__ float sL[128];
    __shared__ float sR[128];

    const int tid = threadIdx.x;
    const int wid = tid >> 5, lid = tid & 31;
    const int g = lid >> 2, q = lid & 3;
    const int warp_m = (wid & 1) * 64, warp_n = (wid >> 1) * 64;
    const int bm = blockIdx.x * 128;

    if (tid < 32) ((float4*)sL)[tid] = __ldg((const float4*)al + tid);
    else if (tid < 64) ((float4*)sR)[tid - 32] = __ldg((const float4*)ar + (tid - 32));

    float acc[4][8][4];
#pragma unroll
    for (int mt = 0; mt < 4; mt++)
#pragma unroll
        for (int nt = 0; nt < 8; nt++)
#pragma unroll
            for (int r = 0; r < 4; r++) acc[mt][nt][r] = 0.f;

    int grow = bm + tid;
    int crow = grow < NN ? grow : NN - 1;
    const float4* ap = (const float4*)(A + (size_t)crow * KD);

    for (int k0 = 0; k0 < KD; k0 += 32) {
        uint16_t* arow_h = sAhi + tid * LDA;
        uint16_t* arow_l = sAlo + tid * LDA;
#pragma unroll
        for (int j = 0; j < 8; j++) {
            float4 v = __ldg(ap + (k0 >> 2) + j);
            __nv_bfloat16 hx = __float2bfloat16_rn(v.x);
            __nv_bfloat16 hy = __float2bfloat16_rn(v.y);
            __nv_bfloat16 hz = __float2bfloat16_rn(v.z);
            __nv_bfloat16 hw = __float2bfloat16_rn(v.w);
            __nv_bfloat162 h0; h0.x = hx; h0.y = hy;
            __nv_bfloat162 h1; h1.x = hz; h1.y = hw;
            __nv_bfloat162 l0 = __floats2bfloat162_rn(v.x - __bfloat162float(hx),
                                                      v.y - __bfloat162float(hy));
            __nv_bfloat162 l1 = __floats2bfloat162_rn(v.z - __bfloat162float(hz),
                                                      v.w - __bfloat162float(hw));
            *(uint32_t*)(arow_h + j * 4)     = *(uint32_t*)&h0;
            *(uint32_t*)(arow_h + j * 4 + 2) = *(uint32_t*)&h1;
            *(uint32_t*)(arow_l + j * 4)     = *(uint32_t*)&l0;
            *(uint32_t*)(arow_l + j * 4 + 2) = *(uint32_t*)&l1;
        }
        {
            const uint4* bh = (const uint4*)(g_Wt_hi + tid * 256 + k0);
            const uint4* bl = (const uint4*)(g_Wt_lo + tid * 256 + k0);
            uint16_t* brow_h = sBhi + tid * LDA;
            uint16_t* brow_l = sBlo + tid * LDA;
#pragma unroll
            for (int j = 0; j < 4; j++) {
                *(uint4*)(brow_h + j * 8) = __ldg(bh + j);
                *(uint4*)(brow_l + j * 8) = __ldg(bl + j);
            }
        }
        __syncthreads();

#pragma unroll
        for (int t = 0; t < 3; t++) {
            const uint16_t* As = (t == 2) ? sAlo : sAhi;
            const uint16_t* Bs = (t == 1) ? sBlo : sBhi;
#pragma unroll
            for (int kk = 0; kk < 32; kk += 16) {
                uint32_t af[4][4], bf[8][2];
#pragma unroll
                for (int mt = 0; mt < 4; mt++) {
                    const uint16_t* p = As + (warp_m + mt * 16 + g) * LDA + kk + q * 2;
                    af[mt][0] = *(const uint32_t*)(p);
                    af[mt][1] = *(const uint32_t*)(p + 8 * LDA);
                    af[mt][2] = *(const uint32_t*)(p + 8);
                    af[mt][3] = *(const uint32_t*)(p + 8 * LDA + 8);
                }
#pragma unroll
                for (int nt = 0; nt < 8; nt++) {
                    const uint16_t* p = Bs + (warp_n + nt * 8 + g) * LDA + kk + q * 2;
                    bf[nt][0] = *(const uint32_t*)(p);
                    bf[nt][1] = *(const uint32_t*)(p + 8);
                }
#pragma unroll
                for (int mt = 0; mt < 4; mt++)
#pragma unroll
                    for (int nt = 0; nt < 8; nt++)
                        mma16816(acc[mt][nt], af[mt], bf[nt]);
            }
        }
        __syncthreads();
    }

    const int hb = warp_n >> 5;
#pragma unroll
    for (int mt = 0; mt < 4; mt++) {
        int r0 = bm + warp_m + mt * 16 + g;
        int r1 = r0 + 8;
        float pel[2][2] = {{0, 0}, {0, 0}};
        float per[2][2] = {{0, 0}, {0, 0}};
#pragma unroll
        for (int nt = 0; nt < 8; nt++) {
            int col = warp_n + nt * 8 + q * 2;
            int hh = nt >> 2;
            float wl0 = sL[col], wl1 = sL[col + 1];
            float wr0 = sR[col], wr1 = sR[col + 1];
            pel[0][hh] += acc[mt][nt][0] * wl0 + acc[mt][nt][1] * wl1;
            per[0][hh] += acc[mt][nt][0] * wr0 + acc[mt][nt][1] * wr1;
            pel[1][hh] += acc[mt][nt][2] * wl0 + acc[mt][nt][3] * wl1;
            per[1][hh] += acc[mt][nt][2] * wr0 + acc[mt][nt][3] * wr1;

            if (r0 < NN) {
                __half2 h2 = __floats2half2_rn(acc[mt][nt][0], acc[mt][nt][1]);
                *(__half2*)(g_feath + (size_t)r0 * FD + col) = h2;
            }
            if (r1 < NN) {
                __half2 h2 = __floats2half2_rn(acc[mt][nt][2], acc[mt][nt][3]);
                *(__half2*)(g_feath + (size_t)r1 * FD + col) = h2;
            }
        }
#pragma unroll
        for (int half = 0; half < 2; half++)
#pragma unroll
            for (int hh = 0; hh < 2; hh++) {
                pel[half][hh] += __shfl_xor_sync(0xffffffffu, pel[half][hh], 1);
                pel[half][hh] += __shfl_xor_sync(0xffffffffu, pel[half][hh], 2);
                per[half][hh] += __shfl_xor_sync(0xffffffffu, per[half][hh], 1);
                per[half][hh] += __shfl_xor_sync(0xffffffffu, per[half][hh], 2);
            }
        if (q == 0) {
            if (r0 < NN) {
                *(float2*)(g_el + r0 * 4 + hb) = make_float2(pel[0][0], pel[0][1]);
                *(float2*)(g_er + r0 * 4 + hb) = make_float2(per[0][0], per[0][1]);
            }
            if (r1 < NN) {
                *(float2*)(g_el + r1 * 4 + hb) = make_float2(pel[1][0], pel[1][1]);
                *(float2*)(g_er + r1 * 4 + hb) = make_float2(per[1][0], per[1][1]);
            }
        }
    }
}

// ---------------------------------------------------------------------------
// CSR build: histogram -> 3-phase exclusive scan -> scatter
// ---------------------------------------------------------------------------
__global__ void k_hist(const int* __restrict__ dst) {
    int e = blockIdx.x * 256 + threadIdx.x;
    if (e >= NE) return;
    atomicAdd(&g_cnt[dst[e]], 1u);
}

__global__ __launch_bounds__(1024) void k_scan1() {
    __shared__ unsigned sh[1024];
    int t = threadIdx.x;
    sh[t] = g_cnt[blockIdx.x * 1024 + t];
    __syncthreads();
    for (int o = 512; o > 0; o >>= 1) {
        if (t < o) sh[t] += sh[t + o];
        __syncthreads();
    }
    if (t == 0) g_bsum[blockIdx.x] = sh[0];
}

__global__ void k_scan2() {
    if (threadIdx.x == 0) {
        unsigned run = 0;
        for (int i = 0; i < NSCAN_BLK; i++) {
            g_bpre[i] = run;
            run += g_bsum[i];
        }
    }
}

__global__ __launch_bounds__(1024) void k_scan3() {
    __shared__ unsigned sh[1024];
    int t = threadIdx.x;
    int i = blockIdx.x * 1024 + t;
    unsigned v = g_cnt[i];
    sh[t] = v;
    __syncthreads();
    for (int o = 1; o < 1024; o <<= 1) {
        unsigned u = (t >= o) ? sh[t - o] : 0u;
        __syncthreads();
        sh[t] += u;
        __syncthreads();
    }
    unsigned exc = sh[t] - v + g_bpre[blockIdx.x];
    g_off[i] = exc;
    g_offw[i] = exc;
}

__global__ void k_scatter(const int* __restrict__ src, const int* __restrict__ dst) {
    int e = blockIdx.x * 256 + threadIdx.x;
    if (e >= NE) return;
    int d = dst[e];
    unsigned pos = atomicAdd(&g_offw[d], 1u);
    g_csrc[pos] = src[e];
}

// ---------------------------------------------------------------------------
// Fused softmax + aggregate: one warp per dst node. Denominator and the full
// 32-float output accumulate in registers; single coalesced store, NO atomics.
// Lane l: heads (ha, ha+2) with ha=l>>4, out dims od=(l&15)*2, +1.
// ---------------------------------------------------------------------------
__global__ __launch_bounds__(256) void k_agg(float* __restrict__ out) {
    int w = (blockIdx.x * 256 + threadIdx.x) >> 5;
    int l = threadIdx.x & 31;
    if (w >= NN) return;
    const int d = w;
    const int beg = (int)g_off[d];
    const int end = (int)g_offw[d];  // == segment end after scatter
    const int ha = l >> 4;

    const float er_a = g_er[d * 4 + ha];
    const float er_b = g_er[d * 4 + ha + 2];
    float den_a = 0.f, den_b = 0.f;
    float2 acc_a = make_float2(0.f, 0.f);
    float2 acc_b = make_float2(0.f, 0.f);

    const int n = end - beg;
    for (int i0 = 0; i0 < n; i0 += 32) {
        int sv = (i0 + l < n) ? __ldg(g_csrc + beg + i0 + l) : 0;
        int lim = min(32, n - i0);
        for (int j = 0; j < lim; j++) {
            int s = __shfl_sync(0xffffffffu, sv, j);
            float el_a = __ldg(g_el + s * 4 + ha);
            float el_b = __ldg(g_el + s * 4 + ha + 2);
            float ex_a = __expf(lrelu(el_a + er_a));
            float ex_b = __expf(lrelu(el_b + er_b));
            den_a += ex_a;
            den_b += ex_b;
            const __half2* fr = (const __half2*)(g_feath + (size_t)s * FD);
            float2 fa = __half22float2(__ldg(fr + l));        // halves 2l..2l+1 (head ha)
            float2 fb = __half22float2(__ldg(fr + 32 + l));   // halves 64+2l (head ha+2)
            acc_a.x += ex_a * fa.x;
            acc_a.y += ex_a * fa.y;
            acc_b.x += ex_b * fb.x;
            acc_b.y += ex_b * fb.y;
        }
    }

    const float inv_a = 0.25f / fmaxf(den_a, 1e-9f);
    const float inv_b = 0.25f / fmaxf(den_b, 1e-9f);
    float rx = acc_a.x * inv_a + acc_b.x * inv_b;
    float ry = acc_a.y * inv_a + acc_b.y * inv_b;
    rx += __shfl_xor_sync(0xffffffffu, rx, 16);
    ry += __shfl_xor_sync(0xffffffffu, ry, 16);
    if (l < 16)
        *(float2*)(out + (size_t)d * OD + l * 2) = make_float2(rx, ry);
}

// ---------------------------------------------------------------------------
extern "C" void kernel_launch(void* const* d_in, const int* in_sizes, int n_in,
                              void* d_out, int out_size) {
    const float* x  = (const float*)d_in[0];
    const float* W  = (const float*)d_in[1];
    const float* al = (const float*)d_in[2];
    const float* ar = (const float*)d_in[3];
    const int* src  = (const int*)d_in[4];
    const int* dst  = (const int*)d_in[5];
    float* out = (float*)d_out;

    k_init<<<(NBIN + 255) / 256, 256>>>();
    k_prep<<<(256 * 128 + 255) / 256, 256>>>(W);
    k_hist<<<(NE + 255) / 256, 256>>>(dst);
    k_gemm_mma<<<(NN + 127) / 128, 128>>>(x, al, ar);
    k_scan1<<<NSCAN_BLK, 1024>>>();
    k_scan2<<<1, 32>>>();
    k_scan3<<<NSCAN_BLK, 1024>>>();
    k_scatter<<<(NE + 255) / 256, 256>>>(src, dst);
    k_agg<<<(NN * 32 + 255) / 256, 256>>>(out);
}

// round 13
// speedup vs baseline: 1.7584x; 1.7584x over previous
#include <cuda_runtime.h>
#include <cuda_bf16.h>
#include <cuda_fp16.h>
#include <stdint.h>

#define NN 100000
#define NE 1600000
#define KD 256
#define FD 128   // HEADS*OUT_DIM
#define OD 32
#define NEG 0.2f

// Scratch (allocation-free rule: __device__ globals)
__device__ __half g_feath[(size_t)NN * FD];  // 25.6 MB fp16 feat
__device__ float g_el[NN * 4];
__device__ float g_er[NN * 4];
__device__ float g_den[NN * 4];
__device__ __nv_bfloat16 g_Wt_hi[128 * 256];
__device__ __nv_bfloat16 g_Wt_lo[128 * 256];

__device__ __forceinline__ float lrelu(float v) { return v > 0.f ? v : NEG * v; }

// ---------------------------------------------------------------------------
__global__ void k_init(float* __restrict__ out) {
    int i = blockIdx.x * 256 + threadIdx.x;
    if (i < NN * OD) out[i] = 0.f;
    if (i < NN * 4) g_den[i] = 0.f;
}

// ---------------------------------------------------------------------------
__global__ void k_prep(const float* __restrict__ W) {
    int i = blockIdx.x * 256 + threadIdx.x;
    if (i >= 256 * 128) return;
    int k = i >> 7, n = i & 127;
    float w = W[i];
    __nv_bfloat16 h = __float2bfloat16_rn(w);
    float l = w - __bfloat162float(h);
    g_Wt_hi[n * 256 + k] = h;
    g_Wt_lo[n * 256 + k] = __float2bfloat16_rn(l);
}

// ---------------------------------------------------------------------------
// HMMA GEMM: 256 threads / 8 warps, CTA tile 128x128, warp tile 32x64.
// 3-term bf16 hi/lo split; fused el/er epilogue; fp16 feat store.
// launch_bounds(256,2): cap regs ~124 -> 2 CTAs/SM = 16 warps (2x round-12 occ).
// ---------------------------------------------------------------------------
#define LDA 40  // padded stride in halves -> conflict-free frag loads

__device__ __forceinline__ void mma16816(float* c, const uint32_t* a, const uint32_t* b) {
    asm volatile(
        "mma.sync.aligned.m16n8k16.row.col.f32.bf16.bf16.f32 "
        "{%0,%1,%2,%3}, {%4,%5,%6,%7}, {%8,%9}, {%0,%1,%2,%3};"
        : "+f"(c[0]), "+f"(c[1]), "+f"(c[2]), "+f"(c[3])
        : "r"(a[0]), "r"(a[1]), "r"(a[2]), "r"(a[3]), "r"(b[0]), "r"(b[1]));
}

__global__ __launch_bounds__(256, 2) void k_gemm_mma(const float* __restrict__ A,
                                                     const float* __restrict__ al,
                                                     const float* __restrict__ ar) {
    __shared__ __align__(16) uint16_t sAhi[128 * LDA];
    __shared__ __align__(16) uint16_t sAlo[128 * LDA];
    __shared__ __align__(16) uint16_t sBhi[128 * LDA];
    __shared__ __align__(16) uint16_t sBlo[128 * LDA];
    __shared__ float sL[128];
    __shared__ float sR[128];

    const int tid = threadIdx.x;
    const int wid = tid >> 5, lid = tid & 31;
    const int g = lid >> 2, q = lid & 3;
    const int warp_m = (wid & 3) * 32;        // 4 warps over M
    const int warp_n = (wid >> 2) * 64;       // 2 warps over N
    const int bm = blockIdx.x * 128;

    if (tid < 32) ((float4*)sL)[tid] = __ldg((const float4*)al + tid);
    else if (tid < 64) ((float4*)sR)[tid - 32] = __ldg((const float4*)ar + (tid - 32));

    float acc[2][8][4];
#pragma unroll
    for (int mt = 0; mt < 2; mt++)
#pragma unroll
        for (int nt = 0; nt < 8; nt++)
#pragma unroll
            for (int r = 0; r < 4; r++) acc[mt][nt][r] = 0.f;

    // staging: thread t handles row t>>1, 16-col half (t&1)
    const int arow = tid >> 1, acol = (tid & 1) * 16;
    int grow = bm + arow;
    int crow = grow < NN ? grow : NN - 1;
    const float* apf = A + (size_t)crow * KD + acol;

    for (int k0 = 0; k0 < KD; k0 += 32) {
        // ---- stage A: 4 float4 -> hi/lo bf16 ----
        uint16_t* arow_h = sAhi + arow * LDA + acol;
        uint16_t* arow_l = sAlo + arow * LDA + acol;
        const float4* ap = (const float4*)(apf + k0);
#pragma unroll
        for (int j = 0; j < 4; j++) {
            float4 v = __ldg(ap + j);
            __nv_bfloat16 hx = __float2bfloat16_rn(v.x);
            __nv_bfloat16 hy = __float2bfloat16_rn(v.y);
            __nv_bfloat16 hz = __float2bfloat16_rn(v.z);
            __nv_bfloat16 hw = __float2bfloat16_rn(v.w);
            __nv_bfloat162 h0; h0.x = hx; h0.y = hy;
            __nv_bfloat162 h1; h1.x = hz; h1.y = hw;
            __nv_bfloat162 l0 = __floats2bfloat162_rn(v.x - __bfloat162float(hx),
                                                      v.y - __bfloat162float(hy));
            __nv_bfloat162 l1 = __floats2bfloat162_rn(v.z - __bfloat162float(hz),
                                                      v.w - __bfloat162float(hw));
            *(uint32_t*)(arow_h + j * 4)     = *(uint32_t*)&h0;
            *(uint32_t*)(arow_h + j * 4 + 2) = *(uint32_t*)&h1;
            *(uint32_t*)(arow_l + j * 4)     = *(uint32_t*)&l0;
            *(uint32_t*)(arow_l + j * 4 + 2) = *(uint32_t*)&l1;
        }
        // ---- stage B: 2 uint4 each of hi/lo ----
        {
            const uint4* bh = (const uint4*)(g_Wt_hi + arow * 256 + k0 + acol);
            const uint4* bl = (const uint4*)(g_Wt_lo + arow * 256 + k0 + acol);
            uint16_t* brow_h = sBhi + arow * LDA + acol;
            uint16_t* brow_l = sBlo + arow * LDA + acol;
#pragma unroll
            for (int j = 0; j < 2; j++) {
                *(uint4*)(brow_h + j * 8) = __ldg(bh + j);
                *(uint4*)(brow_l + j * 8) = __ldg(bl + j);
            }
        }
        __syncthreads();

        // ---- 3 terms x 2 ksteps of 16 ----
#pragma unroll
        for (int t = 0; t < 3; t++) {
            const uint16_t* As = (t == 2) ? sAlo : sAhi;
            const uint16_t* Bs = (t == 1) ? sBlo : sBhi;
#pragma unroll
            for (int kk = 0; kk < 32; kk += 16) {
                uint32_t af[2][4], bf[8][2];
#pragma unroll
                for (int mt = 0; mt < 2; mt++) {
                    const uint16_t* p = As + (warp_m + mt * 16 + g) * LDA + kk + q * 2;
                    af[mt][0] = *(const uint32_t*)(p);
                    af[mt][1] = *(const uint32_t*)(p + 8 * LDA);
                    af[mt][2] = *(const uint32_t*)(p + 8);
                    af[mt][3] = *(const uint32_t*)(p + 8 * LDA + 8);
                }
#pragma unroll
                for (int nt = 0; nt < 8; nt++) {
                    const uint16_t* p = Bs + (warp_n + nt * 8 + g) * LDA + kk + q * 2;
                    bf[nt][0] = *(const uint32_t*)(p);
                    bf[nt][1] = *(const uint32_t*)(p + 8);
                }
#pragma unroll
                for (int mt = 0; mt < 2; mt++)
#pragma unroll
                    for (int nt = 0; nt < 8; nt++)
                        mma16816(acc[mt][nt], af[mt], bf[nt]);
            }
        }
        __syncthreads();
    }

    // ---- store fp16 feat + fused el/er ----
    const int hb = warp_n >> 5;  // head base: 0 or 2
#pragma unroll
    for (int mt = 0; mt < 2; mt++) {
        int r0 = bm + warp_m + mt * 16 + g;
        int r1 = r0 + 8;
        float pel[2][2] = {{0, 0}, {0, 0}};
        float per[2][2] = {{0, 0}, {0, 0}};
#pragma unroll
        for (int nt = 0; nt < 8; nt++) {
            int col = warp_n + nt * 8 + q * 2;
            int hh = nt >> 2;
            float wl0 = sL[col], wl1 = sL[col + 1];
            float wr0 = sR[col], wr1 = sR[col + 1];
            pel[0][hh] += acc[mt][nt][0] * wl0 + acc[mt][nt][1] * wl1;
            per[0][hh] += acc[mt][nt][0] * wr0 + acc[mt][nt][1] * wr1;
            pel[1][hh] += acc[mt][nt][2] * wl0 + acc[mt][nt][3] * wl1;
            per[1][hh] += acc[mt][nt][2] * wr0 + acc[mt][nt][3] * wr1;

            if (r0 < NN) {
                __half2 h2 = __floats2half2_rn(acc[mt][nt][0], acc[mt][nt][1]);
                *(__half2*)(g_feath + (size_t)r0 * FD + col) = h2;
            }
            if (r1 < NN) {
                __half2 h2 = __floats2half2_rn(acc[mt][nt][2], acc[mt][nt][3]);
                *(__half2*)(g_feath + (size_t)r1 * FD + col) = h2;
            }
        }
#pragma unroll
        for (int half = 0; half < 2; half++)
#pragma unroll
            for (int hh = 0; hh < 2; hh++) {
                pel[half][hh] += __shfl_xor_sync(0xffffffffu, pel[half][hh], 1);
                pel[half][hh] += __shfl_xor_sync(0xffffffffu, pel[half][hh], 2);
                per[half][hh] += __shfl_xor_sync(0xffffffffu, per[half][hh], 1);
                per[half][hh] += __shfl_xor_sync(0xffffffffu, per[half][hh], 2);
            }
        if (q == 0) {
            if (r0 < NN) {
                *(float2*)(g_el + r0 * 4 + hb) = make_float2(pel[0][0], pel[0][1]);
                *(float2*)(g_er + r0 * 4 + hb) = make_float2(per[0][0], per[0][1]);
            }
            if (r1 < NN) {
                *(float2*)(g_el + r1 * 4 + hb) = make_float2(pel[1][0], pel[1][1]);
                *(float2*)(g_er + r1 * 4 + hb) = make_float2(per[1][0], per[1][1]);
            }
        }
    }
}

// ---------------------------------------------------------------------------
// Pass B: denom = segment sum of exp(e)  (max-shift cancels algebraically)
// ---------------------------------------------------------------------------
__global__ void k_passB(const int* __restrict__ src, const int* __restrict__ dst) {
    int e = blockIdx.x * 256 + threadIdx.x;
    if (e >= NE) return;
    int s = src[e], d = dst[e];
    float4 el = __ldg((const float4*)(g_el + s * 4));
    float4 er = __ldg((const float4*)(g_er + d * 4));
    float r0 = __expf(lrelu(el.x + er.x));
    float r1 = __expf(lrelu(el.y + er.y));
    float r2 = __expf(lrelu(el.z + er.z));
    float r3 = __expf(lrelu(el.w + er.w));
    asm volatile("red.global.add.v4.f32 [%0], {%1,%2,%3,%4};"
                 :: "l"(g_den + d * 4), "f"(r0), "f"(r1), "f"(r2), "f"(r3)
                 : "memory");
}

// ---------------------------------------------------------------------------
// Pass C: out[dst] += sum_h a_h * feat16[src,h,:] / 4   (head mean folded in)
// ---------------------------------------------------------------------------
__global__ __launch_bounds__(256) void k_passC(const int* __restrict__ src,
                                               const int* __restrict__ dst,
                                               float* __restrict__ out) {
    int t = blockIdx.x * 256 + threadIdx.x;
    int e = t >> 3;
    int sub = t & 7;
    if (e >= NE) return;
    int s = src[e], d = dst[e];
    float4 el = __ldg((const float4*)(g_el + s * 4));
    float4 er = __ldg((const float4*)(g_er + d * 4));
    float4 dn = __ldg((const float4*)(g_den + d * 4));
    float a0 = __expf(lrelu(el.x + er.x)) / fmaxf(dn.x, 1e-9f) * 0.25f;
    float a1 = __expf(lrelu(el.y + er.y)) / fmaxf(dn.y, 1e-9f) * 0.25f;
    float a2 = __expf(lrelu(el.z + er.z)) / fmaxf(dn.z, 1e-9f) * 0.25f;
    float a3 = __expf(lrelu(el.w + er.w)) / fmaxf(dn.w, 1e-9f) * 0.25f;

    const __half* fb = g_feath + (size_t)s * FD + sub * 4;
    __half2 f0a = __ldg((const __half2*)(fb + 0 * OD));
    __half2 f0b = __ldg((const __half2*)(fb + 0 * OD + 2));
    __half2 f1a = __ldg((const __half2*)(fb + 1 * OD));
    __half2 f1b = __ldg((const __half2*)(fb + 1 * OD + 2));
    __half2 f2a = __ldg((const __half2*)(fb + 2 * OD));
    __half2 f2b = __ldg((const __half2*)(fb + 2 * OD + 2));
    __half2 f3a = __ldg((const __half2*)(fb + 3 * OD));
    __half2 f3b = __ldg((const __half2*)(fb + 3 * OD + 2));

    float2 v0a = __half22float2(f0a), v0b = __half22float2(f0b);
    float2 v1a = __half22float2(f1a), v1b = __half22float2(f1b);
    float2 v2a = __half22float2(f2a), v2b = __half22float2(f2b);
    float2 v3a = __half22float2(f3a), v3b = __half22float2(f3b);

    float r0 = a0 * v0a.x + a1 * v1a.x + a2 * v2a.x + a3 * v3a.x;
    float r1 = a0 * v0a.y + a1 * v1a.y + a2 * v2a.y + a3 * v3a.y;
    float r2 = a0 * v0b.x + a1 * v1b.x + a2 * v2b.x + a3 * v3b.x;
    float r3 = a0 * v0b.y + a1 * v1b.y + a2 * v2b.y + a3 * v3b.y;

    float* op = out + (size_t)d * OD + sub * 4;
    asm volatile("red.global.add.v4.f32 [%0], {%1,%2,%3,%4};"
                 :: "l"(op), "f"(r0), "f"(r1), "f"(r2), "f"(r3)
                 : "memory");
}

// ---------------------------------------------------------------------------
extern "C" void kernel_launch(void* const* d_in, const int* in_sizes, int n_in,
                              void* d_out, int out_size) {
    const float* x  = (const float*)d_in[0];
    const float* W  = (const float*)d_in[1];
    const float* al = (const float*)d_in[2];
    const float* ar = (const float*)d_in[3];
    const int* src  = (const int*)d_in[4];
    const int* dst  = (const int*)d_in[5];
    float* out = (float*)d_out;

    k_init<<<(NN * OD + 255) / 256, 256>>>(out);
    k_prep<<<(256 * 128 + 255) / 256, 256>>>(W);
    k_gemm_mma<<<(NN + 127) / 128, 256>>>(x, al, ar);
    k_passB<<<(NE + 255) / 256, 256>>>(src, dst);
    k_passC<<<(NE * 8 + 255) / 256, 256>>>(src, dst, out);
}

// round 16
// speedup vs baseline: 1.8145x; 1.0319x over previous
#include <cuda_runtime.h>
#include <cuda_bf16.h>
#include <cuda_fp16.h>
#include <stdint.h>

#define NN 100000
#define NE 1600000
#define KD 256
#define FD 128   // HEADS*OUT_DIM
#define OD 32
#define NEG 0.2f

// Scratch (allocation-free rule: __device__ globals)
__device__ __half g_feath[(size_t)NN * FD];  // 25.6 MB fp16 feat
__device__ float g_el[NN * 4];
__device__ float g_er[NN * 4];
__device__ float g_den[NN * 4];
__device__ __nv_bfloat16 g_Wt_hi[128 * 256];
__device__ __nv_bfloat16 g_Wt_lo[128 * 256];

__device__ __forceinline__ float lrelu(float v) { return v > 0.f ? v : NEG * v; }

__device__ __forceinline__ void cp_async16(void* smem, const void* gmem) {
    uint32_t s = (uint32_t)__cvta_generic_to_shared(smem);
    asm volatile("cp.async.cg.shared.global [%0], [%1], 16;" :: "r"(s), "l"(gmem));
}

// ---------------------------------------------------------------------------
__global__ void k_init(float* __restrict__ out) {
    int i = blockIdx.x * 256 + threadIdx.x;
    if (i < NN * OD) out[i] = 0.f;
    if (i < NN * 4) g_den[i] = 0.f;
}

// ---------------------------------------------------------------------------
__global__ void k_prep(const float* __restrict__ W) {
    int i = blockIdx.x * 256 + threadIdx.x;
    if (i >= 256 * 128) return;
    int k = i >> 7, n = i & 127;
    float w = W[i];
    __nv_bfloat16 h = __float2bfloat16_rn(w);
    float l = w - __bfloat162float(h);
    g_Wt_hi[n * 256 + k] = h;
    g_Wt_lo[n * 256 + k] = __float2bfloat16_rn(l);
}

// ---------------------------------------------------------------------------
// HMMA GEMM: 256 threads / 8 warps, CTA tile 128x128, warp tile 32x64.
// Pipelined: A prefetched into registers one chunk ahead (LDG overlaps MMA);
// B staged via cp.async (no register round-trip). 3-term bf16 hi/lo split;
// fused el/er epilogue; fp16 feat store. launch_bounds(256,2) -> 2 CTAs/SM.
// ---------------------------------------------------------------------------
#define LDA 40  // padded stride in halves -> conflict-free frag loads

__device__ __forceinline__ void mma16816(float* c, const uint32_t* a, const uint32_t* b) {
    asm volatile(
        "mma.sync.aligned.m16n8k16.row.col.f32.bf16.bf16.f32 "
        "{%0,%1,%2,%3}, {%4,%5,%6,%7}, {%8,%9}, {%0,%1,%2,%3};"
        : "+f"(c[0]), "+f"(c[1]), "+f"(c[2]), "+f"(c[3])
        : "r"(a[0]), "r"(a[1]), "r"(a[2]), "r"(a[3]), "r"(b[0]), "r"(b[1]));
}

__global__ __launch_bounds__(256, 2) void k_gemm_mma(const float* __restrict__ A,
                                                     const float* __restrict__ al,
                                                     const float* __restrict__ ar) {
    __shared__ __align__(16) uint16_t sAhi[128 * LDA];
    __shared__ __align__(16) uint16_t sAlo[128 * LDA];
    __shared__ __align__(16) uint16_t sBhi[128 * LDA];
    __shared__ __align__(16) uint16_t sBlo[128 * LDA];
    __shared__ float sL[128];
    __shared__ float sR[128];

    const int tid = threadIdx.x;
    const int wid = tid >> 5, lid = tid & 31;
    const int g = lid >> 2, q = lid & 3;
    const int warp_m = (wid & 3) * 32;        // 4 warps over M
    const int warp_n = (wid >> 2) * 64;       // 2 warps over N
    const int bm = blockIdx.x * 128;

    if (tid < 32) ((float4*)sL)[tid] = __ldg((const float4*)al + tid);
    else if (tid < 64) ((float4*)sR)[tid - 32] = __ldg((const float4*)ar + (tid - 32));

    float acc[2][8][4];
#pragma unroll
    for (int mt = 0; mt < 2; mt++)
#pragma unroll
        for (int nt = 0; nt < 8; nt++)
#pragma unroll
            for (int r = 0; r < 4; r++) acc[mt][nt][r] = 0.f;

    // staging: thread t handles row t>>1, 16-col half (t&1)
    const int arow = tid >> 1, acol = (tid & 1) * 16;
    int grow = bm + arow;
    int crow = grow < NN ? grow : NN - 1;
    const float* apf = A + (size_t)crow * KD + acol;

    uint16_t* arow_h = sAhi + arow * LDA + acol;
    uint16_t* arow_l = sAlo + arow * LDA + acol;
    uint16_t* brow_h = sBhi + arow * LDA + acol;
    uint16_t* brow_l = sBlo + arow * LDA + acol;
    const __nv_bfloat16* bhp = g_Wt_hi + arow * 256 + acol;
    const __nv_bfloat16* blp = g_Wt_lo + arow * 256 + acol;

    // prefetch chunk 0 A into registers
    float4 va[4];
#pragma unroll
    for (int j = 0; j < 4; j++) va[j] = __ldg((const float4*)apf + j);

    for (int k0 = 0; k0 < KD; k0 += 32) {
        // ---- stage A from prefetched regs: cvt -> hi/lo bf16 -> STS ----
#pragma unroll
        for (int j = 0; j < 4; j++) {
            float4 v = va[j];
            __nv_bfloat16 hx = __float2bfloat16_rn(v.x);
            __nv_bfloat16 hy = __float2bfloat16_rn(v.y);
            __nv_bfloat16 hz = __float2bfloat16_rn(v.z);
            __nv_bfloat16 hw = __float2bfloat16_rn(v.w);
            __nv_bfloat162 h0; h0.x = hx; h0.y = hy;
            __nv_bfloat162 h1; h1.x = hz; h1.y = hw;
            __nv_bfloat162 l0 = __floats2bfloat162_rn(v.x - __bfloat162float(hx),
                                                      v.y - __bfloat162float(hy));
            __nv_bfloat162 l1 = __floats2bfloat162_rn(v.z - __bfloat162float(hz),
                                                      v.w - __bfloat162float(hw));
            *(uint32_t*)(arow_h + j * 4)     = *(uint32_t*)&h0;
            *(uint32_t*)(arow_h + j * 4 + 2) = *(uint32_t*)&h1;
            *(uint32_t*)(arow_l + j * 4)     = *(uint32_t*)&l0;
            *(uint32_t*)(arow_l + j * 4 + 2) = *(uint32_t*)&l1;
        }
        // ---- stage B via cp.async (raw bf16, no regs) ----
        cp_async16(brow_h,     bhp + k0);
        cp_async16(brow_h + 8, bhp + k0 + 8);
        cp_async16(brow_l,     blp + k0);
        cp_async16(brow_l + 8, blp + k0 + 8);
        asm volatile("cp.async.commit_group;");

        // ---- prefetch next A chunk (LDG latency hides under MMA below) ----
        if (k0 + 32 < KD) {
#pragma unroll
            for (int j = 0; j < 4; j++) va[j] = __ldg((const float4*)(apf + k0 + 32) + j);
        }

        asm volatile("cp.async.wait_group 0;");
        __syncthreads();

        // ---- 3 terms x 2 ksteps of 16 ----
#pragma unroll
        for (int t = 0; t < 3; t++) {
            const uint16_t* As = (t == 2) ? sAlo : sAhi;
            const uint16_t* Bs = (t == 1) ? sBlo : sBhi;
#pragma unroll
            for (int kk = 0; kk < 32; kk += 16) {
                uint32_t af[2][4], bf[8][2];
#pragma unroll
                for (int mt = 0; mt < 2; mt++) {
                    const uint16_t* p = As + (warp_m + mt * 16 + g) * LDA + kk + q * 2;
                    af[mt][0] = *(const uint32_t*)(p);
                    af[mt][1] = *(const uint32_t*)(p + 8 * LDA);
                    af[mt][2] = *(const uint32_t*)(p + 8);
                    af[mt][3] = *(const uint32_t*)(p + 8 * LDA + 8);
                }
#pragma unroll
                for (int nt = 0; nt < 8; nt++) {
                    const uint16_t* p = Bs + (warp_n + nt * 8 + g) * LDA + kk + q * 2;
                    bf[nt][0] = *(const uint32_t*)(p);
                    bf[nt][1] = *(const uint32_t*)(p + 8);
                }
#pragma unroll
                for (int mt = 0; mt < 2; mt++)
#pragma unroll
                    for (int nt = 0; nt < 8; nt++)
                        mma16816(acc[mt][nt], af[mt], bf[nt]);
            }
        }
        __syncthreads();
    }

    // ---- store fp16 feat + fused el/er ----
    const int hb = warp_n >> 5;  // head base: 0 or 2
#pragma unroll
    for (int mt = 0; mt < 2; mt++) {
        int r0 = bm + warp_m + mt * 16 + g;
        int r1 = r0 + 8;
        float pel[2][2] = {{0, 0}, {0, 0}};
        float per[2][2] = {{0, 0}, {0, 0}};
#pragma unroll
        for (int nt = 0; nt < 8; nt++) {
            int col = warp_n + nt * 8 + q * 2;
            int hh = nt >> 2;
            float wl0 = sL[col], wl1 = sL[col + 1];
            float wr0 = sR[col], wr1 = sR[col + 1];
            pel[0][hh] += acc[mt][nt][0] * wl0 + acc[mt][nt][1] * wl1;
            per[0][hh] += acc[mt][nt][0] * wr0 + acc[mt][nt][1] * wr1;
            pel[1][hh] += acc[mt][nt][2] * wl0 + acc[mt][nt][3] * wl1;
            per[1][hh] += acc[mt][nt][2] * wr0 + acc[mt][nt][3] * wr1;

            if (r0 < NN) {
                __half2 h2 = __floats2half2_rn(acc[mt][nt][0], acc[mt][nt][1]);
                *(__half2*)(g_feath + (size_t)r0 * FD + col) = h2;
            }
            if (r1 < NN) {
                __half2 h2 = __floats2half2_rn(acc[mt][nt][2], acc[mt][nt][3]);
                *(__half2*)(g_feath + (size_t)r1 * FD + col) = h2;
            }
        }
#pragma unroll
        for (int half = 0; half < 2; half++)
#pragma unroll
            for (int hh = 0; hh < 2; hh++) {
                pel[half][hh] += __shfl_xor_sync(0xffffffffu, pel[half][hh], 1);
                pel[half][hh] += __shfl_xor_sync(0xffffffffu, pel[half][hh], 2);
                per[half][hh] += __shfl_xor_sync(0xffffffffu, per[half][hh], 1);
                per[half][hh] += __shfl_xor_sync(0xffffffffu, per[half][hh], 2);
            }
        if (q == 0) {
            if (r0 < NN) {
                *(float2*)(g_el + r0 * 4 + hb) = make_float2(pel[0][0], pel[0][1]);
                *(float2*)(g_er + r0 * 4 + hb) = make_float2(per[0][0], per[0][1]);
            }
            if (r1 < NN) {
                *(float2*)(g_el + r1 * 4 + hb) = make_float2(pel[1][0], pel[1][1]);
                *(float2*)(g_er + r1 * 4 + hb) = make_float2(per[1][0], per[1][1]);
            }
        }
    }
}

// ---------------------------------------------------------------------------
// Pass B: denom = segment sum of exp(e)  (max-shift cancels algebraically)
// ---------------------------------------------------------------------------
__global__ void k_passB(const int* __restrict__ src, const int* __restrict__ dst) {
    int e = blockIdx.x * 256 + threadIdx.x;
    if (e >= NE) return;
    int s = src[e], d = dst[e];
    float4 el = __ldg((const float4*)(g_el + s * 4));
    float4 er = __ldg((const float4*)(g_er + d * 4));
    float r0 = __expf(lrelu(el.x + er.x));
    float r1 = __expf(lrelu(el.y + er.y));
    float r2 = __expf(lrelu(el.z + er.z));
    float r3 = __expf(lrelu(el.w + er.w));
    asm volatile("red.global.add.v4.f32 [%0], {%1,%2,%3,%4};"
                 :: "l"(g_den + d * 4), "f"(r0), "f"(r1), "f"(r2), "f"(r3)
                 : "memory");
}

// ---------------------------------------------------------------------------
// Pass C: out[dst] += sum_h a_h * feat16[src,h,:] / 4   (head mean folded in)
// ---------------------------------------------------------------------------
__global__ __launch_bounds__(256) void k_passC(const int* __restrict__ src,
                                               const int* __restrict__ dst,
                                               float* __restrict__ out) {
    int t = blockIdx.x * 256 + threadIdx.x;
    int e = t >> 3;
    int sub = t & 7;
    if (e >= NE) return;
    int s = src[e], d = dst[e];
    float4 el = __ldg((const float4*)(g_el + s * 4));
    float4 er = __ldg((const float4*)(g_er + d * 4));
    float4 dn = __ldg((const float4*)(g_den + d * 4));
    float a0 = __expf(lrelu(el.x + er.x)) / fmaxf(dn.x, 1e-9f) * 0.25f;
    float a1 = __expf(lrelu(el.y + er.y)) / fmaxf(dn.y, 1e-9f) * 0.25f;
    float a2 = __expf(lrelu(el.z + er.z)) / fmaxf(dn.z, 1e-9f) * 0.25f;
    float a3 = __expf(lrelu(el.w + er.w)) / fmaxf(dn.w, 1e-9f) * 0.25f;

    const __half* fb = g_feath + (size_t)s * FD + sub * 4;
    __half2 f0a = __ldg((const __half2*)(fb + 0 * OD));
    __half2 f0b = __ldg((const __half2*)(fb + 0 * OD + 2));
    __half2 f1a = __ldg((const __half2*)(fb + 1 * OD));
    __half2 f1b = __ldg((const __half2*)(fb + 1 * OD + 2));
    __half2 f2a = __ldg((const __half2*)(fb + 2 * OD));
    __half2 f2b = __ldg((const __half2*)(fb + 2 * OD + 2));
    __half2 f3a = __ldg((const __half2*)(fb + 3 * OD));
    __half2 f3b = __ldg((const __half2*)(fb + 3 * OD + 2));

    float2 v0a = __half22float2(f0a), v0b = __half22float2(f0b);
    float2 v1a = __half22float2(f1a), v1b = __half22float2(f1b);
    float2 v2a = __half22float2(f2a), v2b = __half22float2(f2b);
    float2 v3a = __half22float2(f3a), v3b = __half22float2(f3b);

    float r0 = a0 * v0a.x + a1 * v1a.x + a2 * v2a.x + a3 * v3a.x;
    float r1 = a0 * v0a.y + a1 * v1a.y + a2 * v2a.y + a3 * v3a.y;
    float r2 = a0 * v0b.x + a1 * v1b.x + a2 * v2b.x + a3 * v3b.x;
    float r3 = a0 * v0b.y + a1 * v1b.y + a2 * v2b.y + a3 * v3b.y;

    float* op = out + (size_t)d * OD + sub * 4;
    asm volatile("red.global.add.v4.f32 [%0], {%1,%2,%3,%4};"
                 :: "l"(op), "f"(r0), "f"(r1), "f"(r2), "f"(r3)
                 : "memory");
}

// ---------------------------------------------------------------------------
extern "C" void kernel_launch(void* const* d_in, const int* in_sizes, int n_in,
                              void* d_out, int out_size) {
    const float* x  = (const float*)d_in[0];
    const float* W  = (const float*)d_in[1];
    const float* al = (const float*)d_in[2];
    const float* ar = (const float*)d_in[3];
    const int* src  = (const int*)d_in[4];
    const int* dst  = (const int*)d_in[5];
    float* out = (float*)d_out;

    k_init<<<(NN * OD + 255) / 256, 256>>>(out);
    k_prep<<<(256 * 128 + 255) / 256, 256>>>(W);
    k_gemm_mma<<<(NN + 127) / 128, 256>>>(x, al, ar);
    k_passB<<<(NE + 255) / 256, 256>>>(src, dst);
    k_passC<<<(NE * 8 + 255) / 256, 256>>>(src, dst, out);
}